// round 8
// baseline (speedup 1.0000x reference)
#include <cuda_runtime.h>
#include <cuda_bf16.h>
#include <cstdint>

// Problem constants (fixed shapes from reference)
#define T_STEPS 32768
#define D_IN    1024
#define U_HID   1024
#define NG      4096   // 4*U

// ---------------- static device scratch (no allocs allowed) ----------------
// zx stored TRANSPOSED: g_zx[col][t]  (col-major in time => per-step reads are
// consecutive-t, sector- and L1-friendly inside the persistent kernel)
__device__ float              g_zx[(size_t)NG * T_STEPS];
// packed hidden state: lo32 = h bits, hi32 = step tag. Double-buffered by parity.
__device__ unsigned long long g_hpk[2][U_HID];

// ============================================================================
// GEMM: zx = x @ kernel + bias   (M=32768, K=1024, N=4096), fp32
// epilogue writes TRANSPOSED: g_zx[col * T + row]
// ============================================================================
#define BM 128
#define BN 128
#define BK 16

__global__ __launch_bounds__(256) void gemm_zx(const float* __restrict__ A,
                                               const float* __restrict__ B,
                                               const float* __restrict__ bias) {
    __shared__ float As[2][BK][BM + 4];
    __shared__ float Bs[2][BK][BN];

    const int tid  = threadIdx.x;
    const int cRow = blockIdx.y * BM;
    const int cCol = blockIdx.x * BN;

    const int aRow  = tid >> 2;
    const int aCol4 = tid & 3;
    const int bRow  = tid >> 5;
    const int bCol4 = tid & 31;

    const int tx = tid & 15, ty = tid >> 4;

    const float* Ap = A + (size_t)cRow * D_IN;
    const float* Bp = B + cCol;

    float acc[8][8];
#pragma unroll
    for (int i = 0; i < 8; ++i)
#pragma unroll
        for (int j = 0; j < 8; ++j) acc[i][j] = 0.f;

    float4 ra0, ra1, rb0, rb1;

    auto loadG = [&](int kt) {
        const size_t ac = (size_t)kt * BK + aCol4 * 4;
        ra0 = *(const float4*)&Ap[(size_t)aRow * D_IN + ac];
        ra1 = *(const float4*)&Ap[(size_t)(aRow + 64) * D_IN + ac];
        rb0 = *(const float4*)&Bp[(size_t)(kt * BK + bRow) * NG + bCol4 * 4];
        rb1 = *(const float4*)&Bp[(size_t)(kt * BK + bRow + 8) * NG + bCol4 * 4];
    };
    auto storeS = [&](int buf) {
        const int k0 = aCol4 * 4;
        As[buf][k0 + 0][aRow] = ra0.x; As[buf][k0 + 1][aRow] = ra0.y;
        As[buf][k0 + 2][aRow] = ra0.z; As[buf][k0 + 3][aRow] = ra0.w;
        As[buf][k0 + 0][aRow + 64] = ra1.x; As[buf][k0 + 1][aRow + 64] = ra1.y;
        As[buf][k0 + 2][aRow + 64] = ra1.z; As[buf][k0 + 3][aRow + 64] = ra1.w;
        *(float4*)&Bs[buf][bRow][bCol4 * 4]     = rb0;
        *(float4*)&Bs[buf][bRow + 8][bCol4 * 4] = rb1;
    };

    loadG(0);
    storeS(0);
    __syncthreads();

    const int nT = D_IN / BK;  // 64
    for (int kt = 0; kt < nT; ++kt) {
        const int buf = kt & 1;
        if (kt + 1 < nT) loadG(kt + 1);
#pragma unroll
        for (int k = 0; k < BK; ++k) {
            float4 a0 = *(const float4*)&As[buf][k][ty * 4];
            float4 a1 = *(const float4*)&As[buf][k][64 + ty * 4];
            float4 b0 = *(const float4*)&Bs[buf][k][tx * 4];
            float4 b1 = *(const float4*)&Bs[buf][k][64 + tx * 4];
            float ar[8] = {a0.x, a0.y, a0.z, a0.w, a1.x, a1.y, a1.z, a1.w};
            float br[8] = {b0.x, b0.y, b0.z, b0.w, b1.x, b1.y, b1.z, b1.w};
#pragma unroll
            for (int i = 0; i < 8; ++i)
#pragma unroll
                for (int j = 0; j < 8; ++j)
                    acc[i][j] = fmaf(ar[i], br[j], acc[i][j]);
        }
        if (kt + 1 < nT) storeS(buf ^ 1);
        __syncthreads();
    }

    float4 bv0 = *(const float4*)&bias[cCol + tx * 4];
    float4 bv1 = *(const float4*)&bias[cCol + 64 + tx * 4];
    float bb[8] = {bv0.x, bv0.y, bv0.z, bv0.w, bv1.x, bv1.y, bv1.z, bv1.w};

#pragma unroll
    for (int i = 0; i < 8; ++i) {
        const int r = cRow + ((i < 4) ? (ty * 4 + i) : (64 + ty * 4 + (i - 4)));
#pragma unroll
        for (int j = 0; j < 8; ++j) {
            const int c = cCol + ((j < 4) ? (tx * 4 + j) : (64 + tx * 4 + (j - 4)));
            g_zx[(size_t)c * T_STEPS + r] = acc[i][j] + bb[j];
        }
    }
}

// ============================================================================
// State init (runs every launch: graph replays reuse device globals)
// ============================================================================
__global__ void init_state() {
    const int i = threadIdx.x;
    g_hpk[0][i] = 0ull;                   // h=0, tag=0 -> step 0 matches instantly
    g_hpk[1][i] = 0x8000000000000000ull;  // tag never matches a real step
}

// ============================================================================
// Persistent recurrent kernel. 128 CTAs x 1024 threads, 1 CTA/SM.
// CTA b owns hidden units [8b, 8b+8) => 32 gate-columns.
//   Arrival: lanes 0..15 of warp w poll PAIRS of packed {h,tag} words with one
//            16B ld.volatile.v2.u64 each (halves L2 poll accesses vs R7).
//   Stage 1: lane l = column (l = 8q+u), warp w = rows [32w,32w+32);
//            h via LDS.128 broadcast; fma.rn.f32x2. Partials -> sp.
//   Stage 2 + gates (warps 0..7 only; warp u owns unit u0+u):
//            lane (q=l>>3, j=l&7) sums 4 partials of column 8q+u
//            (conflict-free banks), 3 bfly shfls -> gate sums on j==0 lanes,
//            + zx, activation in parallel, 3 shfls to lane 0, cell update,
//            publish h (one 8B store) BEFORE out[].
//   Warps 8..31 sleep at barB (no polling => no L2 traffic; R6 failure mode
//   structurally excluded). barB after publish => exchange overlaps barrier.
// ============================================================================
__global__ __launch_bounds__(1024, 1) void lstm_rec(const float* __restrict__ Rw,
                                                    float* __restrict__ out) {
    const int tid = threadIdx.x;
    const int w   = tid >> 5;
    const int l   = tid & 31;
    const int u0  = blockIdx.x * 8;
    // stage-1 column for lane l (CTA column = l = 8q+u)
    const int col = ((l >> 3) << 10) + u0 + (l & 7);

    __shared__ __align__(16) float sh_h[U_HID];
    __shared__ float sp[2][32 * 33];

    // packed weight pairs: W2[m] = {R[32w+2m][col], R[32w+2m+1][col]}
    unsigned long long W2[16];
    {
        const float* wp = Rw + ((size_t)(w << 5)) * NG + col;
#pragma unroll
        for (int m = 0; m < 16; ++m) {
            float w0 = wp[(size_t)(2 * m) * NG];
            float w1 = wp[(size_t)(2 * m + 1) * NG];
            asm("mov.b64 %0, {%1, %2};" : "=l"(W2[m]) : "f"(w0), "f"(w1));
        }
    }

    // reducer role: warps 0..7 (warp u handles unit u0+u); zx loader lanes j==0
    const bool isRed = (w < 8);
    const int  q     = l >> 3;
    const int  j     = l & 7;
    const bool isZ   = isRed && (j == 0);
    // transposed zx: row = q*1024 + u0 + w, walk t contiguously
    const float* zxp = g_zx + ((size_t)((q << 10) + u0 + w)) * T_STEPS;

    float cst = 0.f;                     // cell state (lane 0 of warps 0..7)
    float zxv = isZ ? __ldg(zxp) : 0.f;  // zx for t=0

    for (int t = 0; t < T_STEPS; ++t) {
        // prefetch next step's zx (L1-resident line most steps; off crit path)
        float zxn = 0.f;
        if (isZ && t + 1 < T_STEPS) zxn = __ldg(&zxp[t + 1]);

        // paired poll: lane l<16 waits on elements {32w+2l, 32w+2l+1}
        if (l < 16) {
            const unsigned long long* src = &g_hpk[t & 1][(w << 5) + 2 * l];
            unsigned long long p0, p1;
            do {
                asm volatile("ld.volatile.global.v2.u64 {%0, %1}, [%2];"
                             : "=l"(p0), "=l"(p1) : "l"(src));
            } while (((unsigned)(p0 >> 32) != (unsigned)t) ||
                     ((unsigned)(p1 >> 32) != (unsigned)t));
            float2 hv2 = make_float2(__uint_as_float((unsigned)p0),
                                     __uint_as_float((unsigned)p1));
            *reinterpret_cast<float2*>(&sh_h[(w << 5) + 2 * l]) = hv2;
        }
        __syncwarp();

        float* const spb = sp[t & 1];

        // stage 1: packed-f32x2 partial dot over rows [32w,32w+32) for `col`
        unsigned long long acc0 = 0ull, acc1 = 0ull;
        const ulonglong2* h2 = reinterpret_cast<const ulonglong2*>(sh_h + (w << 5));
#pragma unroll
        for (int k = 0; k < 8; ++k) {
            ulonglong2 hv = h2[k];  // all lanes same address -> smem broadcast
            asm("fma.rn.f32x2 %0, %1, %2, %3;"
                : "=l"(acc0) : "l"(hv.x), "l"(W2[2 * k]),     "l"(acc0));
            asm("fma.rn.f32x2 %0, %1, %2, %3;"
                : "=l"(acc1) : "l"(hv.y), "l"(W2[2 * k + 1]), "l"(acc1));
        }
        float a0, a1, b0, b1;
        asm("mov.b64 {%0, %1}, %2;" : "=f"(a0), "=f"(a1) : "l"(acc0));
        asm("mov.b64 {%0, %1}, %2;" : "=f"(b0), "=f"(b1) : "l"(acc1));
        spb[l * 33 + w] = (a0 + b0) + (a1 + b1);
        __syncthreads();  // bar A: all partials in sp

        // stage 2 + gates: warps 0..7 only (warp w handles unit u0+w)
        if (isRed) {
            const int c = (q << 3) + w;  // CTA column of gate q, unit w
            // 4 partials per lane; bank = (8q + j + w + 8m) & 31: permutation
            const float* spc = spb + c * 33 + j;
            float s = (spc[0] + spc[8]) + (spc[16] + spc[24]);
            // reduce across the 8-lane quarter -> sum on j==0 lanes
            s += __shfl_xor_sync(0xffffffffu, s, 4);
            s += __shfl_xor_sync(0xffffffffu, s, 2);
            s += __shfl_xor_sync(0xffffffffu, s, 1);
            s += zxv;                    // valid on j==0 lanes
            // activation in parallel on the 4 j==0 lanes (q==2 -> tanh)
            const bool tg = (q == 2);
            const float zc = fminf(fmaxf(s, -15.f), 15.f);
            const float ee = __expf(tg ? (2.f * zc) : (-s));
            const float act = tg ? ((ee - 1.f) * __frcp_rn(ee + 1.f))
                                 : __frcp_rn(1.f + ee);
            // gather f, g, o to lane 0
            const float vf = __shfl_xor_sync(0xffffffffu, act, 8);
            const float vg = __shfl_xor_sync(0xffffffffu, act, 16);
            const float vo = __shfl_xor_sync(0xffffffffu, act, 24);
            if (l == 0) {
                const float c2 = vf * cst + act * vg;   // act = i at lane 0
                cst = c2;
                const float cc = fminf(fmaxf(c2, -15.f), 15.f);
                const float ec = __expf(2.f * cc);
                const float h  = vo * ((ec - 1.f) * __frcp_rn(ec + 1.f));
                // publish FIRST: single 8B store carries payload + tag
                unsigned long long pkw;
                asm("mov.b64 %0, {%1, %2};"
                    : "=l"(pkw) : "f"(h), "r"((unsigned)(t + 1)));
                asm volatile("st.volatile.global.u64 [%0], %1;"
                             :: "l"(&g_hpk[(t + 1) & 1][u0 + w]), "l"(pkw)
                             : "memory");
                out[(size_t)t * U_HID + u0 + w] = h;    // off critical path
            }
        }
        __syncthreads();  // bar B: AFTER publish; warps 8..31 sleep here
        zxv = zxn;
    }
}

// ============================================================================
extern "C" void kernel_launch(void* const* d_in, const int* in_sizes, int n_in,
                              void* d_out, int out_size) {
    const float* x    = (const float*)d_in[0];  // [1, 32768, 1024]
    const float* kw   = (const float*)d_in[1];  // [1024, 4096]
    const float* rw   = (const float*)d_in[2];  // [1024, 4096]
    const float* bias = (const float*)d_in[3];  // [4096]
    float* out = (float*)d_out;                 // [1, 32768, 1024]

    dim3 ggrid(NG / BN, T_STEPS / BM);
    gemm_zx<<<ggrid, 256>>>(x, kw, bias);
    init_state<<<1, U_HID>>>();
    lstm_rec<<<128, 1024>>>(rw, out);
}

// round 9
// speedup vs baseline: 1.1550x; 1.1550x over previous
#include <cuda_runtime.h>
#include <cuda_bf16.h>
#include <cstdint>

// Problem constants (fixed shapes from reference)
#define T_STEPS 32768
#define D_IN    1024
#define U_HID   1024
#define NG      4096   // 4*U

#define N_LSTM_CTAS 128
#define ROW_TILES   256   // 32768 / 128
#define COL_TILES   32    // 4096 / 128
#define N_TILES     (ROW_TILES * COL_TILES)

// ---------------- static device scratch (no allocs allowed) ----------------
__device__ float              g_zx[(size_t)T_STEPS * NG];  // x@kernel + bias (row-major by t)
// packed hidden state: lo32 = h bits, hi32 = step tag. Double-buffered by parity.
__device__ unsigned long long g_hpk[2][U_HID];
__device__ unsigned           g_rowready[ROW_TILES];       // per-row-tile completion counters

// ============================================================================
// State init (runs every launch: graph replays reuse device globals)
// ============================================================================
__global__ void init_state() {
    const int i = threadIdx.x;
    if (i < U_HID) {
        g_hpk[0][i] = 0ull;                   // h=0, tag=0 -> step 0 matches instantly
        g_hpk[1][i] = 0x8000000000000000ull;  // tag never matches a real step
    }
    if (i < ROW_TILES) g_rowready[i] = 0u;
}

// ============================================================================
// MEGA-KERNEL: CTAs 0..127 = persistent LSTM recurrence (R7 structure,
// unchanged); CTAs 128.. = GEMM producers computing zx tiles row-tile-major,
// publishing readiness via red.release counters.
// ============================================================================
#define GBM 128
#define GBN 128
#define GBK 16

__global__ __launch_bounds__(1024, 1) void mega(
    const float* __restrict__ x,     // [T, D]
    const float* __restrict__ kw,    // [D, 4U]
    const float* __restrict__ bias,  // [4U]
    const float* __restrict__ Rw,    // [U, 4U]
    float* __restrict__ out,         // [T, U]
    int nGemm)
{
    // ---- shared memory (union by role: each CTA touches only its own set) ----
    __shared__ float As[2][GBK][GBM + 4];
    __shared__ float Bs[2][GBK][GBN];
    __shared__ __align__(16) float sh_h[U_HID];
    __shared__ float sp[2][32 * 33];
    __shared__ float zs[32];

    const int tid = threadIdx.x;

    // ========================== GEMM producer role ==========================
    if (blockIdx.x >= N_LSTM_CTAS) {
        const int rank = blockIdx.x - N_LSTM_CTAS;

        const int aRow = tid >> 3;          // 0..127
        const int ac2  = (tid & 7) * 2;     // 0,2,..,14
        const int bRow = tid >> 6;          // 0..15
        const int bc2  = (tid & 63) * 2;    // 0,2,..,126
        const int tx   = tid & 31;          // col/4
        const int ty   = tid >> 5;          // row/4

        for (int tt = rank; tt < N_TILES; tt += nGemm) {
            const int rowT = tt >> 5;       // row-tile-major => rows ready ascending
            const int colT = tt & 31;
            const int cRow = rowT * GBM;
            const int cCol = colT * GBN;
            const float* Ap = x  + (size_t)cRow * D_IN;
            const float* Bp = kw + cCol;

            float acc[4][4];
#pragma unroll
            for (int i = 0; i < 4; ++i)
#pragma unroll
                for (int j = 0; j < 4; ++j) acc[i][j] = 0.f;

            float2 ra, rb;
            auto loadG = [&](int kt) {
                ra = *(const float2*)&Ap[(size_t)aRow * D_IN + kt * GBK + ac2];
                rb = *(const float2*)&Bp[(size_t)(kt * GBK + bRow) * NG + bc2];
            };
            auto storeS = [&](int buf) {
                As[buf][ac2][aRow]     = ra.x;
                As[buf][ac2 + 1][aRow] = ra.y;
                *(float2*)&Bs[buf][bRow][bc2] = rb;
            };

            loadG(0);
            storeS(0);
            __syncthreads();

            const int nT = D_IN / GBK;  // 64
            for (int kt = 0; kt < nT; ++kt) {
                const int buf = kt & 1;
                if (kt + 1 < nT) loadG(kt + 1);
#pragma unroll
                for (int k = 0; k < GBK; ++k) {
                    float4 av = *(const float4*)&As[buf][k][ty * 4];
                    float4 bv = *(const float4*)&Bs[buf][k][tx * 4];
                    float ar[4] = {av.x, av.y, av.z, av.w};
                    float br[4] = {bv.x, bv.y, bv.z, bv.w};
#pragma unroll
                    for (int i = 0; i < 4; ++i)
#pragma unroll
                        for (int j = 0; j < 4; ++j)
                            acc[i][j] = fmaf(ar[i], br[j], acc[i][j]);
                }
                if (kt + 1 < nT) storeS(buf ^ 1);
                __syncthreads();
            }

            // epilogue: + bias, coalesced float4 stores, row-major by t
            float4 bb4 = *(const float4*)&bias[cCol + tx * 4];
            float bb[4] = {bb4.x, bb4.y, bb4.z, bb4.w};
#pragma unroll
            for (int i = 0; i < 4; ++i) {
                const int r = cRow + ty * 4 + i;
                float4 o = make_float4(acc[i][0] + bb[0], acc[i][1] + bb[1],
                                       acc[i][2] + bb[2], acc[i][3] + bb[3]);
                *(float4*)&g_zx[(size_t)r * NG + cCol + tx * 4] = o;
            }
            __syncthreads();          // all stores of this tile issued
            if (tid == 0) {
                __threadfence();      // gpu-scope: make tile stores visible
                asm volatile("red.release.gpu.global.add.u32 [%0], %1;"
                             :: "l"(&g_rowready[rowT]), "r"(1u) : "memory");
            }
            // next-tile loop re-syncs before smem reuse via the loadG/storeS
            __syncthreads();
        }
        return;
    }

    // ========================== LSTM recurrence role ==========================
    const int w   = tid >> 5;
    const int l   = tid & 31;
    const int u0  = blockIdx.x * 8;
    // stage-1 column for lane l; stage-2 column for warp w
    const int col  = ((l >> 3) << 10) + u0 + (l & 7);
    const int col2 = ((w >> 3) << 10) + u0 + (w & 7);

    // packed weight pairs: W2[m] = {R[32w+2m][col], R[32w+2m+1][col]}
    unsigned long long W2[16];
    {
        const float* wp = Rw + ((size_t)(w << 5)) * NG + col;
#pragma unroll
        for (int m = 0; m < 16; ++m) {
            float w0 = wp[(size_t)(2 * m) * NG];
            float w1 = wp[(size_t)(2 * m + 1) * NG];
            asm("mov.b64 %0, {%1, %2};" : "=l"(W2[m]) : "f"(w0), "f"(w1));
        }
    }

    float cst = 0.f;                       // cell state (warp 0, lanes 0..7)
    const float* zxp = g_zx + col2;

    // zx readiness tracking (only l==0 lanes use it)
    int zreadyT = 0;
    auto wait_tile = [&](int tile) {
        unsigned v;
        do {
            asm volatile("ld.acquire.gpu.global.u32 %0, [%1];"
                         : "=r"(v) : "l"(&g_rowready[tile]) : "memory");
        } while (v < (unsigned)COL_TILES);
    };

    float zxv = 0.f;
    if (l == 0) {               // initial zx (row 0) — wait for tile 0
        wait_tile(0);
        zreadyT = 1;
        zxv = __ldg(zxp);
    }

    const int e = (w << 5) + l;            // element this lane polls

    for (int t = 0; t < T_STEPS; ++t) {
        // prefetch next step's zx early (gated by tile readiness)
        float zxn = 0.f;
        if (l == 0 && t + 1 < T_STEPS) {
            const int tl = (t + 1) >> 7;
            if (tl >= zreadyT) { wait_tile(tl); zreadyT = tl + 1; }
            zxn = __ldg(&zxp[(size_t)(t + 1) * NG]);
        }

        // poll the packed {h, tag} word; tag==t => h is the step-t value
        // (32 contiguous 8B words per warp => coalesced poll, 2 L2 lines)
        {
            const unsigned long long* src = &g_hpk[t & 1][e];
            unsigned long long pk;
            do {
                asm volatile("ld.volatile.global.u64 %0, [%1];"
                             : "=l"(pk) : "l"(src));
            } while ((unsigned)(pk >> 32) != (unsigned)t);
            sh_h[e] = __uint_as_float((unsigned)pk);
        }
        __syncwarp();

        float* const spb = sp[t & 1];      // step-parity buffer

        // stage 1: packed-f32x2 partial dot over rows [32w,32w+32) for `col`
        unsigned long long acc0 = 0ull, acc1 = 0ull;
        const ulonglong2* h2 = reinterpret_cast<const ulonglong2*>(sh_h + (w << 5));
#pragma unroll
        for (int k = 0; k < 8; ++k) {
            ulonglong2 hv = h2[k];  // all lanes same address -> smem broadcast
            asm("fma.rn.f32x2 %0, %1, %2, %3;"
                : "=l"(acc0) : "l"(hv.x), "l"(W2[2 * k]),     "l"(acc0));
            asm("fma.rn.f32x2 %0, %1, %2, %3;"
                : "=l"(acc1) : "l"(hv.y), "l"(W2[2 * k + 1]), "l"(acc1));
        }
        float a0, a1, b0, b1;
        asm("mov.b64 {%0, %1}, %2;" : "=f"(a0), "=f"(a1) : "l"(acc0));
        asm("mov.b64 {%0, %1}, %2;" : "=f"(b0), "=f"(b1) : "l"(acc1));
        spb[l * 33 + w] = (a0 + b0) + (a1 + b1);
        __syncthreads();  // bar A: all partials in sp

        // stage 2: warp w reduces its column across 32 warp-partials
        float v = spb[w * 33 + l];
#pragma unroll
        for (int off = 16; off; off >>= 1)
            v += __shfl_xor_sync(0xffffffffu, v, off);
        if (l == 0) zs[w] = v + zxv;
        __syncthreads();  // bar B: gate pre-activations ready

        // gates: warp 0, lane 8q+u computes activation of gate q, unit u
        if (w == 0) {
            const float z  = zs[l];
            const int   q  = l >> 3;
            const bool  tg = (q == 2);
            const float zc = fminf(fmaxf(z, -15.f), 15.f);
            const float ee = __expf(tg ? (2.f * zc) : (-z));
            const float act = tg ? ((ee - 1.f) / (ee + 1.f))
                                 : (1.f / (1.f + ee));
            // deliver f,g,o to lanes 0..7 (3 independent bfly shfls)
            const float vf = __shfl_xor_sync(0xffffffffu, act, 8);
            const float vg = __shfl_xor_sync(0xffffffffu, act, 16);
            const float vo = __shfl_xor_sync(0xffffffffu, act, 24);
            if (l < 8) {
                const float c2 = vf * cst + act * vg;   // act = i on lanes 0..7
                cst = c2;
                const float cc = fminf(fmaxf(c2, -15.f), 15.f);
                const float ec = __expf(2.f * cc);
                const float h  = vo * ((ec - 1.f) / (ec + 1.f));
                // publish FIRST: one coalesced 64B wavefront (8 lanes x 8B)
                unsigned long long pkw;
                asm("mov.b64 %0, {%1, %2};"
                    : "=l"(pkw) : "f"(h), "r"((unsigned)(t + 1)));
                asm volatile("st.volatile.global.u64 [%0], %1;"
                             :: "l"(&g_hpk[(t + 1) & 1][u0 + l]), "l"(pkw)
                             : "memory");
                out[(size_t)t * U_HID + u0 + l] = h;    // off critical path
            }
        }
        zxv = zxn;
        // no trailing barrier: zs(t+1) writes happen after bar A(t+1), which
        // warp 0 only reaches after gates; sp reuse is parity-buffered.
    }
}

// ============================================================================
extern "C" void kernel_launch(void* const* d_in, const int* in_sizes, int n_in,
                              void* d_out, int out_size) {
    const float* x    = (const float*)d_in[0];  // [1, 32768, 1024]
    const float* kw   = (const float*)d_in[1];  // [1024, 4096]
    const float* rw   = (const float*)d_in[2];  // [1024, 4096]
    const float* bias = (const float*)d_in[3];  // [4096]
    float* out = (float*)d_out;                 // [1, 32768, 1024]

    int sms = 148;
    cudaDeviceGetAttribute(&sms, cudaDevAttrMultiProcessorCount, 0);
    int nGemm = sms - N_LSTM_CTAS;              // producer CTAs on spare SMs
    if (nGemm < 1) nGemm = 1;

    init_state<<<1, 1024>>>();
    mega<<<N_LSTM_CTAS + nGemm, 1024>>>(x, kw, bias, rw, out, nGemm);
}